// round 8
// baseline (speedup 1.0000x reference)
#include <cuda_runtime.h>

#define BB 1024
#define AA 64
#define GG 31
#define WWIN 8
#define HH 512
#define SS 32
#define DKK 32
#define K3H 1536

// ---------------- scratch (static device globals; no allocation) ----------------
__device__ float g_brics[(size_t)BB * SS * K3H];   // 201 MB
__device__ float g_ffrag[(size_t)BB * SS * HH];    // 64 MB
__device__ float g_hs0[(size_t)BB * HH];           // 2 MB

// ---------------- f32x2 helpers (B300 dual-fp32 pipe) ----------------
__device__ __forceinline__ unsigned long long dup2(float a) {
    unsigned long long r;
    asm("mov.b64 %0, {%1, %1};" : "=l"(r) : "f"(a));
    return r;
}
__device__ __forceinline__ unsigned long long fma2(unsigned long long a,
                                                   unsigned long long b,
                                                   unsigned long long c) {
    unsigned long long d;
    asm("fma.rn.f32x2 %0, %1, %2, %3;" : "=l"(d) : "l"(a), "l"(b), "l"(c));
    return d;
}
__device__ __forceinline__ float2 unpack2(unsigned long long v) {
    float2 f;
    asm("mov.b64 {%0, %1}, %2;" : "=f"(f.x), "=f"(f.y) : "l"(v));
    return f;
}

// ---------------- Kernel 1: build brics = [fg ; sum|max|group] ----------------
// NOTE: mapping is int32 (JAX x64 disabled => jnp.int64 request yields int32).
__global__ __launch_bounds__(128) void build_brics(
    const float* __restrict__ f_atom, const float* __restrict__ f_group,
    const float* __restrict__ fg, const int* __restrict__ mapping) {
    int bs = blockIdx.x;
    int b = bs >> 5, s = bs & 31;
    int tid = threadIdx.x;
    float* dst = g_brics + (size_t)bs * K3H;
    if (s == 0) {
        const float4* src = (const float4*)fg;
        float4* d4 = (float4*)dst;
        for (int i = tid; i < K3H / 4; i += 128) d4[i] = src[i];
        return;
    }
    int g = s - 1;
    const int* mp = mapping + ((size_t)b * GG + g) * WWIN;
    int idx[WWIN];
    #pragma unroll
    for (int w = 0; w < WWIN; w++) idx[w] = mp[w];
    float4 sm = make_float4(0.f, 0.f, 0.f, 0.f);
    float4 mx = make_float4(-3.4e38f, -3.4e38f, -3.4e38f, -3.4e38f);
    #pragma unroll
    for (int w = 0; w < WWIN; w++) {
        float4 v;
        if (idx[w] == 0) {
            v = make_float4(0.f, 0.f, 0.f, 0.f);
        } else {
            v = ((const float4*)(f_atom + ((size_t)b * AA + idx[w] - 1) * HH))[tid];
        }
        sm.x += v.x; sm.y += v.y; sm.z += v.z; sm.w += v.w;
        mx.x = fmaxf(mx.x, v.x); mx.y = fmaxf(mx.y, v.y);
        mx.z = fmaxf(mx.z, v.z); mx.w = fmaxf(mx.w, v.w);
    }
    ((float4*)dst)[tid] = sm;
    ((float4*)(dst + HH))[tid] = mx;
    ((float4*)(dst + 2 * HH))[tid] =
        ((const float4*)(f_group + ((size_t)b * GG + g) * HH))[tid];
}

// ---------------- tiled SGEMM body, f32x2 accumulators ----------------
// C[M,N] = A[M,K] @ B[K,N] + bias[N], optional ReLU. M,N mult of 128, K mult of 8.
template <bool RELU>
__device__ __forceinline__ void sgemm_body(
    const float* __restrict__ A, const float* __restrict__ Bm,
    const float* __restrict__ bias, float* __restrict__ C,
    int M, int N, int K) {
    __shared__ float As[8][128];
    __shared__ float Bs[8][128];
    int tid = threadIdx.x;
    int m0 = blockIdx.y * 128, n0 = blockIdx.x * 128;
    int ar = tid >> 1, ac = (tid & 1) * 4;
    int br = tid >> 5, bc = (tid & 31) * 4;
    int tx = tid & 15, ty = tid >> 4;
    unsigned long long cc[8][4];
    #pragma unroll
    for (int i = 0; i < 8; i++)
        #pragma unroll
        for (int j = 0; j < 4; j++) cc[i][j] = 0ull;  // (+0.f, +0.f)
    const float* Aptr = A + (size_t)(m0 + ar) * K + ac;
    const float* Bptr = Bm + (size_t)br * N + n0 + bc;
    for (int k0 = 0; k0 < K; k0 += 8) {
        float4 a4 = *(const float4*)(Aptr + k0);
        float4 b4 = *(const float4*)(Bptr + (size_t)k0 * N);
        As[ac + 0][ar] = a4.x; As[ac + 1][ar] = a4.y;
        As[ac + 2][ar] = a4.z; As[ac + 3][ar] = a4.w;
        *(float4*)&Bs[br][bc] = b4;
        __syncthreads();
        #pragma unroll
        for (int k = 0; k < 8; k++) {
            float4 a0 = *(const float4*)&As[k][ty * 8];
            float4 a1 = *(const float4*)&As[k][ty * 8 + 4];
            const unsigned long long* bp =
                (const unsigned long long*)&Bs[k][tx * 8];
            unsigned long long b0 = bp[0], b1 = bp[1], b2 = bp[2], b3 = bp[3];
            float av[8] = {a0.x, a0.y, a0.z, a0.w, a1.x, a1.y, a1.z, a1.w};
            #pragma unroll
            for (int i = 0; i < 8; i++) {
                unsigned long long ad = dup2(av[i]);
                cc[i][0] = fma2(ad, b0, cc[i][0]);
                cc[i][1] = fma2(ad, b1, cc[i][1]);
                cc[i][2] = fma2(ad, b2, cc[i][2]);
                cc[i][3] = fma2(ad, b3, cc[i][3]);
            }
        }
        __syncthreads();
    }
    #pragma unroll
    for (int i = 0; i < 8; i++) {
        int row = m0 + ty * 8 + i;
        float* crow = C + (size_t)row * N + n0 + tx * 8;
        #pragma unroll
        for (int j = 0; j < 4; j++) {
            float2 v = unpack2(cc[i][j]);
            int col = n0 + tx * 8 + 2 * j;
            v.x += bias[col];
            v.y += bias[col + 1];
            if (RELU) { v.x = fmaxf(v.x, 0.f); v.y = fmaxf(v.y, 0.f); }
            *(float2*)&crow[2 * j] = v;
        }
    }
}

__global__ __launch_bounds__(256, 2) void sgemm_brics(
    const float* __restrict__ lr_w, const float* __restrict__ lr_b) {
    sgemm_body<true>(g_brics, lr_w, lr_b, g_ffrag, BB * SS, HH, K3H);
}
__global__ __launch_bounds__(256, 2) void sgemm_final(
    const float* __restrict__ lin_w, const float* __restrict__ lin_b,
    float* __restrict__ out) {
    sgemm_body<false>(g_hs0, lin_w, lin_b, out, BB, HH, HH);
}

// ---------------- Kernel 3: per-batch transformer (2 layers) ----------------
// Flat decomposition: every cross-thread dataflow crosses __syncthreads().
#define ATH 256
#define PAD33 33
#define A_HS   (SS * HH)     // 16384
#define A_Q    (SS * PAD33)  // 1056
#define A_K    (SS * PAD33)
#define A_V    (SS * PAD33)
#define A_P    (SS * PAD33)
#define A_X    (SS * PAD33)
#define A_PM   (SS * 17)     // 544 unsigned
#define ATTN_SMEM_FLOATS (A_HS + 5 * A_Q + A_PM)

__global__ __launch_bounds__(ATH) void attn_kernel(
    const float* __restrict__ wq_w, const float* __restrict__ wq_b,
    const float* __restrict__ wk_w, const float* __restrict__ wk_b,
    const float* __restrict__ wv_w, const float* __restrict__ wv_b,
    const float* __restrict__ dense_w, const float* __restrict__ dense_b,
    const float* __restrict__ ln_g, const float* __restrict__ ln_b,
    float* __restrict__ out) {
    extern __shared__ float sm[];
    float* hs = sm;                 // [32][512]
    float* q  = hs + A_HS;          // [32][33]
    float* kk = q + A_Q;            // [32][33]
    float* vv = kk + A_K;           // [32][33]
    float* pp = vv + A_V;           // [32][33] scores -> probs
    float* xx = pp + A_P;           // [32][33]
    unsigned* pm = (unsigned*)(xx + A_X);  // [32][17]

    int b = blockIdx.x;
    int tid = threadIdx.x, w = tid >> 5, lane = tid & 31;

    // ---- load hs = f_frag[b] ----
    {
        const float4* src = (const float4*)(g_ffrag + (size_t)b * SS * HH);
        float4* dst = (float4*)hs;
        for (int i = tid; i < SS * HH / 4; i += ATH) dst[i] = src[i];
    }
    __syncthreads();

    // ---- pm bitmasks (mask from layer-0 input only) ----
    for (int t = w; t < 512; t += 8) {
        int s = t >> 4, c = t & 15;
        unsigned bits = __ballot_sync(0xffffffffu, hs[s * HH + c * 32 + lane] > 0.f);
        if (lane == 0) pm[s * 17 + c] = bits;
    }
    __syncthreads();

    for (int l = 0; l < 2; l++) {
        // ---- q, k, v : one (s,d) pair per virtual thread ----
        #pragma unroll
        for (int j = 0; j < 4; j++) {
            int idx = tid + ATH * j;
            int s = idx >> 5, d = idx & 31;
            const float* hrow = hs + s * HH;
            const float* wq = wq_w + (size_t)l * HH * DKK + d;
            const float* wk = wk_w + (size_t)l * HH * DKK + d;
            const float* wv = wv_w + (size_t)l * HH * DKK + d;
            float aq = wq_b[l * DKK + d];
            float ak = wk_b[l * DKK + d];
            float av = wv_b[l * DKK + d];
            #pragma unroll 8
            for (int t = 0; t < HH; t++) {
                float h = hrow[t];
                aq = fmaf(h, wq[t * DKK], aq);
                ak = fmaf(h, wk[t * DKK], ak);
                av = fmaf(h, wv[t * DKK], av);
            }
            q[s * PAD33 + d] = aq;
            kk[s * PAD33 + d] = ak;
            vv[s * PAD33 + d] = av;
        }
        __syncthreads();

        // ---- masked scores: one (s,t) pair per virtual thread ----
        #pragma unroll
        for (int j = 0; j < 4; j++) {
            int idx = tid + ATH * j;
            int s = idx >> 5, t = idx & 31;
            float a = 0.f;
            #pragma unroll 8
            for (int d = 0; d < 32; d++)
                a = fmaf(q[s * PAD33 + d], kk[t * PAD33 + d], a);
            a *= 0.17677669529663687f;   // 1/sqrt(32)
            unsigned ored = 0;
            #pragma unroll
            for (int i = 0; i < 16; i++) ored |= pm[s * 17 + i] & pm[t * 17 + i];
            pp[s * PAD33 + t] = ored ? a : -1e9f;
        }
        __syncthreads();

        // ---- softmax per row: warp w handles rows s = w + 8i ----
        #pragma unroll
        for (int i = 0; i < 4; i++) {
            int s = w + 8 * i;
            float a = pp[s * PAD33 + lane];
            float mval = a;
            #pragma unroll
            for (int o = 16; o > 0; o >>= 1)
                mval = fmaxf(mval, __shfl_xor_sync(0xffffffffu, mval, o));
            float e = __expf(a - mval);
            float ssum = e;
            #pragma unroll
            for (int o = 16; o > 0; o >>= 1)
                ssum += __shfl_xor_sync(0xffffffffu, ssum, o);
            float pr = e / ssum;
            pp[s * PAD33 + lane] = pr;
            if (l == 1)
                out[(size_t)BB * HH + ((size_t)b * SS + s) * SS + lane] = pr;
        }
        __syncthreads();

        // ---- x = p @ v : one (s,d) pair per virtual thread ----
        #pragma unroll
        for (int j = 0; j < 4; j++) {
            int idx = tid + ATH * j;
            int s = idx >> 5, d = idx & 31;
            float a = 0.f;
            #pragma unroll 8
            for (int t = 0; t < 32; t++)
                a = fmaf(pp[s * PAD33 + t], vv[t * PAD33 + d], a);
            xx[s * PAD33 + d] = a;
        }
        __syncthreads();

        // ---- dense + residual: one (s,h) per virtual thread ----
        for (int j = 0; j < 64; j++) {
            int idx = tid + ATH * j;
            int s = idx >> 9, h = idx & 511;
            float a = dense_b[l * HH + h];
            const float* dw = dense_w + (size_t)l * DKK * HH + h;
            const float* xrow = xx + s * PAD33;
            #pragma unroll 8
            for (int n = 0; n < 32; n++)
                a = fmaf(xrow[n], dw[n * HH], a);
            hs[s * HH + h] += a;
        }
        __syncthreads();

        // ---- layernorm per row (eps 1e-6): warp w rows s = w + 8i ----
        #pragma unroll
        for (int i = 0; i < 4; i++) {
            int s = w + 8 * i;
            float* row = hs + s * HH;
            float sum = 0.f;
            #pragma unroll
            for (int jj = 0; jj < 16; jj++) sum += row[lane + 32 * jj];
            #pragma unroll
            for (int o = 16; o > 0; o >>= 1)
                sum += __shfl_xor_sync(0xffffffffu, sum, o);
            float mu = sum * (1.f / 512.f);
            float vsum = 0.f;
            #pragma unroll
            for (int jj = 0; jj < 16; jj++) {
                float dq = row[lane + 32 * jj] - mu;
                vsum = fmaf(dq, dq, vsum);
            }
            #pragma unroll
            for (int o = 16; o > 0; o >>= 1)
                vsum += __shfl_xor_sync(0xffffffffu, vsum, o);
            float rstd = rsqrtf(vsum * (1.f / 512.f) + 1e-6f);
            #pragma unroll
            for (int jj = 0; jj < 16; jj++) {
                int h = lane + 32 * jj;
                row[h] = ln_g[l * HH + h] * (row[h] - mu) * rstd + ln_b[l * HH + h];
            }
        }
        __syncthreads();
    }
    // only row 0 feeds the final projection
    g_hs0[(size_t)b * HH + tid] = hs[tid];
    g_hs0[(size_t)b * HH + tid + 256] = hs[tid + 256];
}

// ---------------- Kernel 5: final layernorm * alpha (in-place on d_out) ----------------
__global__ __launch_bounds__(256) void final_ln(
    const float* __restrict__ ng, const float* __restrict__ nb,
    const float* __restrict__ alpha, float* __restrict__ out) {
    __shared__ float red[16];
    int b = blockIdx.x, tid = threadIdx.x, w = tid >> 5, lane = tid & 31;
    float* row = out + (size_t)b * HH;
    float v0 = row[tid], v1 = row[tid + 256];
    float sum = v0 + v1;
    #pragma unroll
    for (int o = 16; o > 0; o >>= 1) sum += __shfl_xor_sync(0xffffffffu, sum, o);
    if (lane == 0) red[w] = sum;
    __syncthreads();
    if (tid == 0) {
        float t = 0.f;
        #pragma unroll
        for (int i = 0; i < 8; i++) t += red[i];
        red[8] = t * (1.f / 512.f);
    }
    __syncthreads();
    float mu = red[8];
    float d0 = v0 - mu, d1 = v1 - mu;
    float qq = d0 * d0 + d1 * d1;
    #pragma unroll
    for (int o = 16; o > 0; o >>= 1) qq += __shfl_xor_sync(0xffffffffu, qq, o);
    if (lane == 0) red[w] = qq;
    __syncthreads();
    if (tid == 0) {
        float t = 0.f;
        #pragma unroll
        for (int i = 0; i < 8; i++) t += red[i];
        red[9] = rsqrtf(t * (1.f / 512.f) + 1e-5f);
    }
    __syncthreads();
    float rstd = red[9];
    float a = alpha[0];
    row[tid] = (ng[tid] * d0 * rstd + nb[tid]) * a;
    row[tid + 256] = (ng[tid + 256] * d1 * rstd + nb[tid + 256]) * a;
}

// ---------------- launcher ----------------
extern "C" void kernel_launch(void* const* d_in, const int* in_sizes, int n_in,
                              void* d_out, int out_size) {
    const float* f_atom   = (const float*)d_in[0];
    const float* f_group  = (const float*)d_in[1];
    const float* fg       = (const float*)d_in[2];
    const float* alpha    = (const float*)d_in[3];
    const float* lr_w     = (const float*)d_in[4];
    const float* lr_b     = (const float*)d_in[5];
    const float* wq_w     = (const float*)d_in[6];
    const float* wq_b     = (const float*)d_in[7];
    const float* wk_w     = (const float*)d_in[8];
    const float* wk_b     = (const float*)d_in[9];
    const float* wv_w     = (const float*)d_in[10];
    const float* wv_b     = (const float*)d_in[11];
    const float* dense_w  = (const float*)d_in[12];
    const float* dense_b  = (const float*)d_in[13];
    const float* ln_g     = (const float*)d_in[14];
    const float* ln_b     = (const float*)d_in[15];
    const float* lin_w    = (const float*)d_in[16];
    const float* lin_b    = (const float*)d_in[17];
    const float* norm_g   = (const float*)d_in[18];
    const float* norm_b   = (const float*)d_in[19];
    const int* mapping    = (const int*)d_in[20];   // int32! (JAX x64 disabled)
    float* out = (float*)d_out;

    const int attn_smem = ATTN_SMEM_FLOATS * 4;   // 88832 bytes
    cudaFuncSetAttribute(attn_kernel, cudaFuncAttributeMaxDynamicSharedMemorySize,
                         attn_smem);

    // 1) brics
    build_brics<<<BB * SS, 128>>>(f_atom, f_group, fg, mapping);

    // 2) f_frag = relu(brics @ lr_w + lr_b)   M=32768 N=512 K=1536
    sgemm_brics<<<dim3(HH / 128, (BB * SS) / 128), 256>>>(lr_w, lr_b);

    // 3) transformer (writes attn to out tail, hs row0 to g_hs0)
    attn_kernel<<<BB, ATH, attn_smem>>>(wq_w, wq_b, wk_w, wk_b, wv_w, wv_b,
                                        dense_w, dense_b, ln_g, ln_b, out);

    // 4) lin: out[0:B*H] = hs0 @ lin_w + lin_b   M=1024 N=512 K=512
    sgemm_final<<<dim3(HH / 128, BB / 128), 256>>>(lin_w, lin_b, out);

    // 5) final layernorm * alpha (in place)
    final_ln<<<BB, 256>>>(norm_g, norm_b, alpha, out);
}

// round 11
// speedup vs baseline: 1.2521x; 1.2521x over previous
#include <cuda_runtime.h>
#include <cuda_bf16.h>
#include <cstdint>

#define BB 1024
#define AA 64
#define GG 31
#define WWIN 8
#define HH 512
#define SS 32
#define DKK 32
#define K3H 1536

// ---------------- scratch (static device globals; no allocation) ----------------
__device__ unsigned short g_a_hi[(size_t)BB * SS * K3H];   // brics hi  (100.7 MB)
__device__ unsigned short g_a_lo[(size_t)BB * SS * K3H];   // brics lo
__device__ float          g_ffrag[(size_t)BB * SS * HH];   // f_frag fp32 (64 MB)
__device__ unsigned short g_h0_hi[(size_t)BB * HH];        // hs row0 hi
__device__ unsigned short g_h0_lo[(size_t)BB * HH];
__device__ unsigned short g_wb_hi[(size_t)HH * K3H];       // lr_w  [n][k] hi
__device__ unsigned short g_wb_lo[(size_t)HH * K3H];
__device__ unsigned short g_wf_hi[(size_t)HH * HH];        // lin_w [n][k] hi
__device__ unsigned short g_wf_lo[(size_t)HH * HH];

// ---------------- bf16 split helpers ----------------
__device__ __forceinline__ unsigned short f2bf(float f) {
    return __bfloat16_as_ushort(__float2bfloat16(f));
}
__device__ __forceinline__ float bf2f(unsigned short u) {
    return __bfloat162float(__ushort_as_bfloat16(u));
}

// mma.sync m16n8k16 bf16 (baseline PTX, valid on compute_103 -> HMMA)
__device__ __forceinline__ void mma16816(float* c, const uint32_t* a,
                                         const uint32_t* b) {
    asm volatile(
        "mma.sync.aligned.m16n8k16.row.col.f32.bf16.bf16.f32 "
        "{%0,%1,%2,%3}, {%4,%5,%6,%7}, {%8,%9}, {%0,%1,%2,%3};"
        : "+f"(c[0]), "+f"(c[1]), "+f"(c[2]), "+f"(c[3])
        : "r"(a[0]), "r"(a[1]), "r"(a[2]), "r"(a[3]), "r"(b[0]), "r"(b[1]));
}

// ---------------- Kernel 0: one-time weight transpose+split (tiny) ----------------
__global__ __launch_bounds__(256) void convert_weights(
    const float* __restrict__ lr_w, const float* __restrict__ lin_w) {
    int t = blockIdx.x * 256 + threadIdx.x;
    if (t < K3H * HH) {               // lr_w[k][n] -> g_wb[n][k]
        int k = t / HH, n = t % HH;
        float f = lr_w[t];
        unsigned short h = f2bf(f);
        g_wb_hi[(size_t)n * K3H + k] = h;
        g_wb_lo[(size_t)n * K3H + k] = f2bf(f - bf2f(h));
    }
    if (t < HH * HH) {                // lin_w[k][n] -> g_wf[n][k]
        int k = t / HH, n = t % HH;
        float f = lin_w[t];
        unsigned short h = f2bf(f);
        g_wf_hi[(size_t)n * HH + k] = h;
        g_wf_lo[(size_t)n * HH + k] = f2bf(f - bf2f(h));
    }
}

// ---------------- Kernel 1: build brics (bf16 hi/lo output) ----------------
// mapping is int32 (JAX x64 disabled).
__global__ __launch_bounds__(128) void build_brics(
    const float* __restrict__ f_atom, const float* __restrict__ f_group,
    const float* __restrict__ fg, const int* __restrict__ mapping) {
    int bs = blockIdx.x;
    int b = bs >> 5, s = bs & 31;
    int tid = threadIdx.x;     // 128 threads, one float4 lane per 512-section
    unsigned short* dh = g_a_hi + (size_t)bs * K3H;
    unsigned short* dl = g_a_lo + (size_t)bs * K3H;

    float4 secs[3];
    if (s == 0) {
        secs[0] = ((const float4*)fg)[tid];
        secs[1] = ((const float4*)fg)[tid + 128];
        secs[2] = ((const float4*)fg)[tid + 256];
    } else {
        int g = s - 1;
        const int* mp = mapping + ((size_t)b * GG + g) * WWIN;
        int idx[WWIN];
        #pragma unroll
        for (int w = 0; w < WWIN; w++) idx[w] = mp[w];
        float4 sm = make_float4(0.f, 0.f, 0.f, 0.f);
        float4 mx = make_float4(-3.4e38f, -3.4e38f, -3.4e38f, -3.4e38f);
        #pragma unroll
        for (int w = 0; w < WWIN; w++) {
            float4 v;
            if (idx[w] == 0) v = make_float4(0.f, 0.f, 0.f, 0.f);
            else v = ((const float4*)(f_atom + ((size_t)b * AA + idx[w] - 1) * HH))[tid];
            sm.x += v.x; sm.y += v.y; sm.z += v.z; sm.w += v.w;
            mx.x = fmaxf(mx.x, v.x); mx.y = fmaxf(mx.y, v.y);
            mx.z = fmaxf(mx.z, v.z); mx.w = fmaxf(mx.w, v.w);
        }
        secs[0] = sm;
        secs[1] = mx;
        secs[2] = ((const float4*)(f_group + ((size_t)b * GG + g) * HH))[tid];
    }
    #pragma unroll
    for (int sec = 0; sec < 3; sec++) {
        float v[4] = {secs[sec].x, secs[sec].y, secs[sec].z, secs[sec].w};
        unsigned short h[4], l[4];
        #pragma unroll
        for (int j = 0; j < 4; j++) {
            h[j] = f2bf(v[j]);
            l[j] = f2bf(v[j] - bf2f(h[j]));
        }
        int off = sec * HH + tid * 4;
        *(uint2*)(dh + off) = make_uint2((uint32_t)h[0] | ((uint32_t)h[1] << 16),
                                         (uint32_t)h[2] | ((uint32_t)h[3] << 16));
        *(uint2*)(dl + off) = make_uint2((uint32_t)l[0] | ((uint32_t)l[1] << 16),
                                         (uint32_t)l[2] | ((uint32_t)l[3] << 16));
    }
}

// ---------------- mma.sync split-bf16 GEMM ----------------
// C[M,512] = A[M,KTOT] @ W[KTOT,512] + bias, optional ReLU.
// A hi/lo bf16 row-major [m][k]; W hi/lo bf16 [n][k] (k contiguous).
// CTA tile 128x128, BK=64; 8 warps of 64x32.
#define GSTR 72   // padded smem stride in b16 (144 B, conflict-free frag loads)
#define TCSM_BYTES (4 * 128 * GSTR * 2)   // Ah,Al,Bh,Bl = 73728

template <bool RELU, int KTOT, int SRC>
__global__ __launch_bounds__(256) void gemm_mma(
    const float* __restrict__ bias, float* __restrict__ Cout) {
    extern __shared__ unsigned short smem[];
    unsigned short* Ah = smem;                    // [128][GSTR]
    unsigned short* Al = Ah + 128 * GSTR;
    unsigned short* Bh = Al + 128 * GSTR;
    unsigned short* Bl = Bh + 128 * GSTR;

    const unsigned short* Agh = (SRC == 0) ? g_a_hi : g_h0_hi;
    const unsigned short* Agl = (SRC == 0) ? g_a_lo : g_h0_lo;
    const unsigned short* Wgh = (SRC == 0) ? g_wb_hi : g_wf_hi;
    const unsigned short* Wgl = (SRC == 0) ? g_wb_lo : g_wf_lo;
    float* Cp = (SRC == 0) ? g_ffrag : Cout;

    int tid = threadIdx.x, wid = tid >> 5, lane = tid & 31;
    int m0 = blockIdx.y * 128, n0 = blockIdx.x * 128;
    int wm = (wid & 1) * 64;          // warp m offset within CTA tile
    int wn = (wid >> 1) * 32;         // warp n offset

    float acc[4][4][4];
    #pragma unroll
    for (int i = 0; i < 4; i++)
        #pragma unroll
        for (int j = 0; j < 4; j++)
            #pragma unroll
            for (int c = 0; c < 4; c++) acc[i][j][c] = 0.f;

    int g = lane >> 2, tg = lane & 3;  // fragment group id / thread-in-group

    for (int kc = 0; kc < KTOT / 64; kc++) {
        // stage A/B chunks (128 rows x 64 b16 each, hi+lo)
        #pragma unroll
        for (int i = tid; i < 1024; i += 256) {
            int r = i >> 3, c8 = (i & 7) * 8;
            size_t ga = (size_t)(m0 + r) * KTOT + kc * 64 + c8;
            size_t gb = (size_t)(n0 + r) * KTOT + kc * 64 + c8;
            int so = r * GSTR + c8;
            *(uint4*)(Ah + so) = *(const uint4*)(Agh + ga);
            *(uint4*)(Al + so) = *(const uint4*)(Agl + ga);
            *(uint4*)(Bh + so) = *(const uint4*)(Wgh + gb);
            *(uint4*)(Bl + so) = *(const uint4*)(Wgl + gb);
        }
        __syncthreads();

        #pragma unroll
        for (int ks = 0; ks < 4; ks++) {
            int kbase = ks * 16 + 2 * tg;
            // B fragments (4 n-frags, hi+lo)
            uint32_t bh[4][2], bl[4][2];
            #pragma unroll
            for (int nf = 0; nf < 4; nf++) {
                int n = wn + nf * 8 + g;
                bh[nf][0] = *(const uint32_t*)(Bh + n * GSTR + kbase);
                bh[nf][1] = *(const uint32_t*)(Bh + n * GSTR + kbase + 8);
                bl[nf][0] = *(const uint32_t*)(Bl + n * GSTR + kbase);
                bl[nf][1] = *(const uint32_t*)(Bl + n * GSTR + kbase + 8);
            }
            #pragma unroll
            for (int mf = 0; mf < 4; mf++) {
                int r = wm + mf * 16 + g;
                uint32_t ah[4], al[4];
                ah[0] = *(const uint32_t*)(Ah + r * GSTR + kbase);
                ah[1] = *(const uint32_t*)(Ah + (r + 8) * GSTR + kbase);
                ah[2] = *(const uint32_t*)(Ah + r * GSTR + kbase + 8);
                ah[3] = *(const uint32_t*)(Ah + (r + 8) * GSTR + kbase + 8);
                al[0] = *(const uint32_t*)(Al + r * GSTR + kbase);
                al[1] = *(const uint32_t*)(Al + (r + 8) * GSTR + kbase);
                al[2] = *(const uint32_t*)(Al + r * GSTR + kbase + 8);
                al[3] = *(const uint32_t*)(Al + (r + 8) * GSTR + kbase + 8);
                #pragma unroll
                for (int nf = 0; nf < 4; nf++) {
                    mma16816(acc[mf][nf], ah, bh[nf]);   // hi*hi
                    mma16816(acc[mf][nf], ah, bl[nf]);   // hi*lo
                    mma16816(acc[mf][nf], al, bh[nf]);   // lo*hi
                }
            }
        }
        __syncthreads();
    }

    // epilogue: C fragment c0,c1 -> (row g, cols 2tg+0/1); c2,c3 -> row g+8
    #pragma unroll
    for (int mf = 0; mf < 4; mf++) {
        #pragma unroll
        for (int nf = 0; nf < 4; nf++) {
            int row = m0 + wm + mf * 16 + g;
            int col = n0 + wn + nf * 8 + 2 * tg;
            float b0 = bias[col], b1 = bias[col + 1];
            float2 v0 = make_float2(acc[mf][nf][0] + b0, acc[mf][nf][1] + b1);
            float2 v1 = make_float2(acc[mf][nf][2] + b0, acc[mf][nf][3] + b1);
            if (RELU) {
                v0.x = fmaxf(v0.x, 0.f); v0.y = fmaxf(v0.y, 0.f);
                v1.x = fmaxf(v1.x, 0.f); v1.y = fmaxf(v1.y, 0.f);
            }
            *(float2*)(Cp + (size_t)row * HH + col) = v0;
            *(float2*)(Cp + (size_t)(row + 8) * HH + col) = v1;
        }
    }
}

// ---------------- Kernel 3: per-batch transformer (2 layers) ----------------
#define ATH 256
#define PAD33 33
#define A_HS   (SS * HH)
#define A_Q    (SS * PAD33)
#define A_PM   (SS * 17)
#define ATTN_SMEM_FLOATS (A_HS + 5 * A_Q + A_PM)

__global__ __launch_bounds__(ATH) void attn_kernel(
    const float* __restrict__ wq_w, const float* __restrict__ wq_b,
    const float* __restrict__ wk_w, const float* __restrict__ wk_b,
    const float* __restrict__ wv_w, const float* __restrict__ wv_b,
    const float* __restrict__ dense_w, const float* __restrict__ dense_b,
    const float* __restrict__ ln_g, const float* __restrict__ ln_b,
    float* __restrict__ out) {
    extern __shared__ float sm[];
    float* hs = sm;
    float* q  = hs + A_HS;
    float* kk = q + A_Q;
    float* vv = kk + A_Q;
    float* pp = vv + A_Q;
    float* xx = pp + A_Q;
    unsigned* pm = (unsigned*)(xx + A_Q);

    int b = blockIdx.x;
    int tid = threadIdx.x, w = tid >> 5, lane = tid & 31;

    {
        const float4* src = (const float4*)(g_ffrag + (size_t)b * SS * HH);
        float4* dst = (float4*)hs;
        for (int i = tid; i < SS * HH / 4; i += ATH) dst[i] = src[i];
    }
    __syncthreads();

    for (int t = w; t < 512; t += 8) {
        int s = t >> 4, c = t & 15;
        unsigned bits = __ballot_sync(0xffffffffu, hs[s * HH + c * 32 + lane] > 0.f);
        if (lane == 0) pm[s * 17 + c] = bits;
    }
    __syncthreads();

    for (int l = 0; l < 2; l++) {
        #pragma unroll
        for (int j = 0; j < 4; j++) {
            int idx = tid + ATH * j;
            int s = idx >> 5, d = idx & 31;
            const float* hrow = hs + s * HH;
            const float* wq = wq_w + (size_t)l * HH * DKK + d;
            const float* wk = wk_w + (size_t)l * HH * DKK + d;
            const float* wv = wv_w + (size_t)l * HH * DKK + d;
            float aq = wq_b[l * DKK + d];
            float ak = wk_b[l * DKK + d];
            float av = wv_b[l * DKK + d];
            #pragma unroll 8
            for (int t = 0; t < HH; t++) {
                float h = hrow[t];
                aq = fmaf(h, wq[t * DKK], aq);
                ak = fmaf(h, wk[t * DKK], ak);
                av = fmaf(h, wv[t * DKK], av);
            }
            q[s * PAD33 + d] = aq;
            kk[s * PAD33 + d] = ak;
            vv[s * PAD33 + d] = av;
        }
        __syncthreads();

        #pragma unroll
        for (int j = 0; j < 4; j++) {
            int idx = tid + ATH * j;
            int s = idx >> 5, t = idx & 31;
            float a = 0.f;
            #pragma unroll 8
            for (int d = 0; d < 32; d++)
                a = fmaf(q[s * PAD33 + d], kk[t * PAD33 + d], a);
            a *= 0.17677669529663687f;
            unsigned ored = 0;
            #pragma unroll
            for (int i = 0; i < 16; i++) ored |= pm[s * 17 + i] & pm[t * 17 + i];
            pp[s * PAD33 + t] = ored ? a : -1e9f;
        }
        __syncthreads();

        #pragma unroll
        for (int i = 0; i < 4; i++) {
            int s = w + 8 * i;
            float a = pp[s * PAD33 + lane];
            float mval = a;
            #pragma unroll
            for (int o = 16; o > 0; o >>= 1)
                mval = fmaxf(mval, __shfl_xor_sync(0xffffffffu, mval, o));
            float e = __expf(a - mval);
            float ssum = e;
            #pragma unroll
            for (int o = 16; o > 0; o >>= 1)
                ssum += __shfl_xor_sync(0xffffffffu, ssum, o);
            float pr = e / ssum;
            pp[s * PAD33 + lane] = pr;
            if (l == 1)
                out[(size_t)BB * HH + ((size_t)b * SS + s) * SS + lane] = pr;
        }
        __syncthreads();

        #pragma unroll
        for (int j = 0; j < 4; j++) {
            int idx = tid + ATH * j;
            int s = idx >> 5, d = idx & 31;
            float a = 0.f;
            #pragma unroll 8
            for (int t = 0; t < 32; t++)
                a = fmaf(pp[s * PAD33 + t], vv[t * PAD33 + d], a);
            xx[s * PAD33 + d] = a;
        }
        __syncthreads();

        for (int j = 0; j < 64; j++) {
            int idx = tid + ATH * j;
            int s = idx >> 9, h = idx & 511;
            float a = dense_b[l * HH + h];
            const float* dw = dense_w + (size_t)l * DKK * HH + h;
            const float* xrow = xx + s * PAD33;
            #pragma unroll 8
            for (int n = 0; n < 32; n++)
                a = fmaf(xrow[n], dw[n * HH], a);
            hs[s * HH + h] += a;
        }
        __syncthreads();

        #pragma unroll
        for (int i = 0; i < 4; i++) {
            int s = w + 8 * i;
            float* row = hs + s * HH;
            float sum = 0.f;
            #pragma unroll
            for (int jj = 0; jj < 16; jj++) sum += row[lane + 32 * jj];
            #pragma unroll
            for (int o = 16; o > 0; o >>= 1)
                sum += __shfl_xor_sync(0xffffffffu, sum, o);
            float mu = sum * (1.f / 512.f);
            float vsum = 0.f;
            #pragma unroll
            for (int jj = 0; jj < 16; jj++) {
                float dq = row[lane + 32 * jj] - mu;
                vsum = fmaf(dq, dq, vsum);
            }
            #pragma unroll
            for (int o = 16; o > 0; o >>= 1)
                vsum += __shfl_xor_sync(0xffffffffu, vsum, o);
            float rstd = rsqrtf(vsum * (1.f / 512.f) + 1e-6f);
            #pragma unroll
            for (int jj = 0; jj < 16; jj++) {
                int h = lane + 32 * jj;
                row[h] = ln_g[l * HH + h] * (row[h] - mu) * rstd + ln_b[l * HH + h];
            }
        }
        __syncthreads();
    }
    // only row 0 feeds the final projection; store as bf16 hi/lo
    {
        float v0 = hs[tid], v1 = hs[tid + 256];
        unsigned short h0 = f2bf(v0), h1 = f2bf(v1);
        g_h0_hi[(size_t)b * HH + tid] = h0;
        g_h0_lo[(size_t)b * HH + tid] = f2bf(v0 - bf2f(h0));
        g_h0_hi[(size_t)b * HH + tid + 256] = h1;
        g_h0_lo[(size_t)b * HH + tid + 256] = f2bf(v1 - bf2f(h1));
    }
}

// ---------------- Kernel 5: final layernorm * alpha (in-place on d_out) ----------------
__global__ __launch_bounds__(256) void final_ln(
    const float* __restrict__ ng, const float* __restrict__ nb,
    const float* __restrict__ alpha, float* __restrict__ out) {
    __shared__ float red[16];
    int b = blockIdx.x, tid = threadIdx.x, w = tid >> 5, lane = tid & 31;
    float* row = out + (size_t)b * HH;
    float v0 = row[tid], v1 = row[tid + 256];
    float sum = v0 + v1;
    #pragma unroll
    for (int o = 16; o > 0; o >>= 1) sum += __shfl_xor_sync(0xffffffffu, sum, o);
    if (lane == 0) red[w] = sum;
    __syncthreads();
    if (tid == 0) {
        float t = 0.f;
        #pragma unroll
        for (int i = 0; i < 8; i++) t += red[i];
        red[8] = t * (1.f / 512.f);
    }
    __syncthreads();
    float mu = red[8];
    float d0 = v0 - mu, d1 = v1 - mu;
    float qq = d0 * d0 + d1 * d1;
    #pragma unroll
    for (int o = 16; o > 0; o >>= 1) qq += __shfl_xor_sync(0xffffffffu, qq, o);
    if (lane == 0) red[w] = qq;
    __syncthreads();
    if (tid == 0) {
        float t = 0.f;
        #pragma unroll
        for (int i = 0; i < 8; i++) t += red[i];
        red[9] = rsqrtf(t * (1.f / 512.f) + 1e-5f);
    }
    __syncthreads();
    float rstd = red[9];
    float a = alpha[0];
    row[tid] = (ng[tid] * d0 * rstd + nb[tid]) * a;
    row[tid + 256] = (ng[tid + 256] * d1 * rstd + nb[tid + 256]) * a;
}

// ---------------- launcher ----------------
extern "C" void kernel_launch(void* const* d_in, const int* in_sizes, int n_in,
                              void* d_out, int out_size) {
    const float* f_atom   = (const float*)d_in[0];
    const float* f_group  = (const float*)d_in[1];
    const float* fg       = (const float*)d_in[2];
    const float* alpha    = (const float*)d_in[3];
    const float* lr_w     = (const float*)d_in[4];
    const float* lr_b     = (const float*)d_in[5];
    const float* wq_w     = (const float*)d_in[6];
    const float* wq_b     = (const float*)d_in[7];
    const float* wk_w     = (const float*)d_in[8];
    const float* wk_b     = (const float*)d_in[9];
    const float* wv_w     = (const float*)d_in[10];
    const float* wv_b     = (const float*)d_in[11];
    const float* dense_w  = (const float*)d_in[12];
    const float* dense_b  = (const float*)d_in[13];
    const float* ln_g     = (const float*)d_in[14];
    const float* ln_b     = (const float*)d_in[15];
    const float* lin_w    = (const float*)d_in[16];
    const float* lin_b    = (const float*)d_in[17];
    const float* norm_g   = (const float*)d_in[18];
    const float* norm_b   = (const float*)d_in[19];
    const int* mapping    = (const int*)d_in[20];   // int32 (JAX x64 disabled)
    float* out = (float*)d_out;

    const int attn_smem = ATTN_SMEM_FLOATS * 4;
    cudaFuncSetAttribute(attn_kernel, cudaFuncAttributeMaxDynamicSharedMemorySize,
                         attn_smem);
    cudaFuncSetAttribute(gemm_mma<true, K3H, 0>,
                         cudaFuncAttributeMaxDynamicSharedMemorySize, TCSM_BYTES);
    cudaFuncSetAttribute(gemm_mma<false, HH, 1>,
                         cudaFuncAttributeMaxDynamicSharedMemorySize, TCSM_BYTES);

    // 0) weights -> transposed bf16 hi/lo
    convert_weights<<<(K3H * HH) / 256, 256>>>(lr_w, lin_w);

    // 1) brics (bf16 hi/lo)
    build_brics<<<BB * SS, 128>>>(f_atom, f_group, fg, mapping);

    // 2) f_frag = relu(brics @ lr_w + lr_b)  via mma.sync split-bf16
    gemm_mma<true, K3H, 0><<<dim3(4, (BB * SS) / 128), 256, TCSM_BYTES>>>(lr_b,
                                                                          nullptr);

    // 3) transformer (writes attn to out tail, hs row0 hi/lo to g_h0)
    attn_kernel<<<BB, ATH, attn_smem>>>(wq_w, wq_b, wk_w, wk_b, wv_w, wv_b,
                                        dense_w, dense_b, ln_g, ln_b, out);

    // 4) lin: out[0:B*H] = hs0 @ lin_w + lin_b  via mma.sync split-bf16
    gemm_mma<false, HH, 1><<<dim3(4, BB / 128), 256, TCSM_BYTES>>>(lin_b, out);

    // 5) final layernorm * alpha (in place)
    final_ln<<<BB, 256>>>(norm_g, norm_b, alpha, out);
}

// round 14
// speedup vs baseline: 2.1224x; 1.6951x over previous
#include <cuda_runtime.h>
#include <cuda_bf16.h>
#include <cstdint>

#define BB 1024
#define AA 64
#define GG 31
#define WWIN 8
#define HH 512
#define SS 32
#define DKK 32
#define K3H 1536

// ---------------- scratch (static device globals; no allocation) ----------------
__device__ unsigned short g_a_hi[(size_t)BB * SS * K3H];   // brics hi
__device__ unsigned short g_a_lo[(size_t)BB * SS * K3H];   // brics lo
__device__ float          g_hs_f32[(size_t)BB * SS * HH];  // current hs (fp32)
__device__ unsigned short g_hs_hi[(size_t)BB * SS * HH];   // current hs bf16 split
__device__ unsigned short g_hs_lo[(size_t)BB * SS * HH];
__device__ float          g_qkv[(size_t)BB * SS * 128];    // packed q|k|v (+pad)
__device__ unsigned short g_x_hi[(size_t)BB * SS * 64];    // attn x, zero-padded K
__device__ unsigned short g_x_lo[(size_t)BB * SS * 64];
__device__ float          g_dh[(size_t)BB * SS * HH];      // dense output
__device__ unsigned int   g_pm[(size_t)BB * SS * 16];      // sign bitmasks
__device__ unsigned short g_wb_hi[(size_t)HH * K3H];       // lr_w  [n][k]
__device__ unsigned short g_wb_lo[(size_t)HH * K3H];
__device__ unsigned short g_wf_hi[(size_t)HH * HH];        // lin_w [n][k]
__device__ unsigned short g_wf_lo[(size_t)HH * HH];
__device__ unsigned short g_wqkv_hi[(size_t)2 * 128 * HH]; // qkv packed [l][n][k]
__device__ unsigned short g_wqkv_lo[(size_t)2 * 128 * HH];
__device__ float          g_bqkv[2 * 128];                 // qkv packed bias
__device__ unsigned short g_wd_hi[(size_t)2 * HH * 64];    // dense [l][n][64pad]
__device__ unsigned short g_wd_lo[(size_t)2 * HH * 64];

// ---------------- bf16 split helpers ----------------
__device__ __forceinline__ unsigned short f2bf(float f) {
    return __bfloat16_as_ushort(__float2bfloat16(f));
}
__device__ __forceinline__ float bf2f(unsigned short u) {
    return __bfloat162float(__ushort_as_bfloat16(u));
}

// mma.sync m16n8k16 bf16 (baseline PTX -> HMMA on sm_103)
__device__ __forceinline__ void mma16816(float* c, const uint32_t* a,
                                         const uint32_t* b) {
    asm volatile(
        "mma.sync.aligned.m16n8k16.row.col.f32.bf16.bf16.f32 "
        "{%0,%1,%2,%3}, {%4,%5,%6,%7}, {%8,%9}, {%0,%1,%2,%3};"
        : "+f"(c[0]), "+f"(c[1]), "+f"(c[2]), "+f"(c[3])
        : "r"(a[0]), "r"(a[1]), "r"(a[2]), "r"(a[3]), "r"(b[0]), "r"(b[1]));
}

// ---------------- Kernel 0: one-time weight packing/splitting ----------------
__global__ __launch_bounds__(256) void convert_weights(
    const float* __restrict__ lr_w, const float* __restrict__ lin_w,
    const float* __restrict__ wq_w, const float* __restrict__ wq_b,
    const float* __restrict__ wk_w, const float* __restrict__ wk_b,
    const float* __restrict__ wv_w, const float* __restrict__ wv_b,
    const float* __restrict__ dense_w) {
    int t = blockIdx.x * 256 + threadIdx.x;
    if (t < K3H * HH) {               // lr_w[k][n] -> g_wb[n][k]
        int k = t / HH, n = t % HH;
        float f = lr_w[t];
        unsigned short h = f2bf(f);
        g_wb_hi[(size_t)n * K3H + k] = h;
        g_wb_lo[(size_t)n * K3H + k] = f2bf(f - bf2f(h));
    }
    if (t < HH * HH) {                // lin_w[k][n] -> g_wf[n][k]
        int k = t / HH, n = t % HH;
        float f = lin_w[t];
        unsigned short h = f2bf(f);
        g_wf_hi[(size_t)n * HH + k] = h;
        g_wf_lo[(size_t)n * HH + k] = f2bf(f - bf2f(h));
    }
    if (t < 2 * 128 * HH) {           // qkv pack: [l][n][k], rows 96..127 zero
        int l = t / (128 * HH);
        int r = t % (128 * HH);
        int n = r / HH, k = r % HH;
        float f = 0.f;
        if (n < 32)       f = wq_w[(size_t)l * HH * DKK + k * DKK + n];
        else if (n < 64)  f = wk_w[(size_t)l * HH * DKK + k * DKK + (n - 32)];
        else if (n < 96)  f = wv_w[(size_t)l * HH * DKK + k * DKK + (n - 64)];
        unsigned short h = f2bf(f);
        g_wqkv_hi[t] = h;
        g_wqkv_lo[t] = f2bf(f - bf2f(h));
    }
    if (t < 2 * 128) {                // qkv packed bias
        int l = t / 128, n = t % 128;
        float f = 0.f;
        if (n < 32)       f = wq_b[l * DKK + n];
        else if (n < 64)  f = wk_b[l * DKK + (n - 32)];
        else if (n < 96)  f = wv_b[l * DKK + (n - 64)];
        g_bqkv[t] = f;
    }
    if (t < 2 * HH * 64) {            // dense pack: [l][n][64], k>=32 zero
        int l = t / (HH * 64);
        int r = t % (HH * 64);
        int n = r / 64, k = r % 64;
        float f = (k < DKK) ? dense_w[(size_t)l * DKK * HH + k * HH + n] : 0.f;
        unsigned short h = f2bf(f);
        g_wd_hi[t] = h;
        g_wd_lo[t] = f2bf(f - bf2f(h));
    }
}

// ---------------- Kernel 1: build brics (bf16 hi/lo) ----------------
// mapping is int32 (JAX x64 disabled).
__global__ __launch_bounds__(128) void build_brics(
    const float* __restrict__ f_atom, const float* __restrict__ f_group,
    const float* __restrict__ fg, const int* __restrict__ mapping) {
    int bs = blockIdx.x;
    int b = bs >> 5, s = bs & 31;
    int tid = threadIdx.x;
    unsigned short* dh = g_a_hi + (size_t)bs * K3H;
    unsigned short* dl = g_a_lo + (size_t)bs * K3H;

    float4 secs[3];
    if (s == 0) {
        secs[0] = ((const float4*)fg)[tid];
        secs[1] = ((const float4*)fg)[tid + 128];
        secs[2] = ((const float4*)fg)[tid + 256];
    } else {
        int g = s - 1;
        const int* mp = mapping + ((size_t)b * GG + g) * WWIN;
        int idx[WWIN];
        #pragma unroll
        for (int w = 0; w < WWIN; w++) idx[w] = mp[w];
        float4 sm = make_float4(0.f, 0.f, 0.f, 0.f);
        float4 mx = make_float4(-3.4e38f, -3.4e38f, -3.4e38f, -3.4e38f);
        #pragma unroll
        for (int w = 0; w < WWIN; w++) {
            float4 v;
            if (idx[w] == 0) v = make_float4(0.f, 0.f, 0.f, 0.f);
            else v = ((const float4*)(f_atom + ((size_t)b * AA + idx[w] - 1) * HH))[tid];
            sm.x += v.x; sm.y += v.y; sm.z += v.z; sm.w += v.w;
            mx.x = fmaxf(mx.x, v.x); mx.y = fmaxf(mx.y, v.y);
            mx.z = fmaxf(mx.z, v.z); mx.w = fmaxf(mx.w, v.w);
        }
        secs[0] = sm;
        secs[1] = mx;
        secs[2] = ((const float4*)(f_group + ((size_t)b * GG + g) * HH))[tid];
    }
    #pragma unroll
    for (int sec = 0; sec < 3; sec++) {
        float v[4] = {secs[sec].x, secs[sec].y, secs[sec].z, secs[sec].w};
        unsigned short h[4], l[4];
        #pragma unroll
        for (int j = 0; j < 4; j++) {
            h[j] = f2bf(v[j]);
            l[j] = f2bf(v[j] - bf2f(h[j]));
        }
        int off = sec * HH + tid * 4;
        *(uint2*)(dh + off) = make_uint2((uint32_t)h[0] | ((uint32_t)h[1] << 16),
                                         (uint32_t)h[2] | ((uint32_t)h[3] << 16));
        *(uint2*)(dl + off) = make_uint2((uint32_t)l[0] | ((uint32_t)l[1] << 16),
                                         (uint32_t)l[2] | ((uint32_t)l[3] << 16));
    }
}

// ---------------- mma.sync split-bf16 GEMM (4 modes) ----------------
// MODE 0: hs = relu(brics@lr_w+lr_b) [KTOT=1536] + write hi/lo split
// MODE 1: qkv = hs@Wqkv+bqkv         [KTOT=512, CSTRIDE=128]
// MODE 2: out = hs[s=0]@lin_w+lin_b  [KTOT=512, A row stride 32*512]
// MODE 3: dh  = x@Wd+dense_b         [KTOT=64]
#define GSTR 72
#define TCSM_BYTES (4 * 128 * GSTR * 2)   // 73728

template <int MODE>
__global__ __launch_bounds__(256) void gemm_mma(
    const float* __restrict__ bias, float* __restrict__ Cout, int layer) {
    constexpr int KTOT = (MODE == 0) ? K3H : (MODE == 3) ? 64 : HH;
    constexpr bool RELU = (MODE == 0);
    constexpr int CSTRIDE = (MODE == 1) ? 128 : HH;

    extern __shared__ unsigned short smem[];
    unsigned short* Ah = smem;
    unsigned short* Al = Ah + 128 * GSTR;
    unsigned short* Bh = Al + 128 * GSTR;
    unsigned short* Bl = Bh + 128 * GSTR;

    const unsigned short* Agh;
    const unsigned short* Agl;
    const unsigned short* Wgh;
    const unsigned short* Wgl;
    float* Cp;
    if (MODE == 0) { Agh = g_a_hi;  Agl = g_a_lo;  Wgh = g_wb_hi; Wgl = g_wb_lo; Cp = g_hs_f32; }
    else if (MODE == 1) {
        Agh = g_hs_hi; Agl = g_hs_lo;
        Wgh = g_wqkv_hi + (size_t)layer * 128 * HH;
        Wgl = g_wqkv_lo + (size_t)layer * 128 * HH;
        Cp = g_qkv;
    } else if (MODE == 2) { Agh = g_hs_hi; Agl = g_hs_lo; Wgh = g_wf_hi; Wgl = g_wf_lo; Cp = Cout; }
    else {
        Agh = g_x_hi; Agl = g_x_lo;
        Wgh = g_wd_hi + (size_t)layer * HH * 64;
        Wgl = g_wd_lo + (size_t)layer * HH * 64;
        Cp = g_dh;
    }

    int tid = threadIdx.x, wid = tid >> 5, lane = tid & 31;
    int m0 = blockIdx.y * 128, n0 = blockIdx.x * 128;
    int wm = (wid & 1) * 64;
    int wn = (wid >> 1) * 32;

    float acc[4][4][4];
    #pragma unroll
    for (int i = 0; i < 4; i++)
        #pragma unroll
        for (int j = 0; j < 4; j++)
            #pragma unroll
            for (int c = 0; c < 4; c++) acc[i][j][c] = 0.f;

    int g = lane >> 2, tg = lane & 3;

    for (int kc = 0; kc < KTOT / 64; kc++) {
        #pragma unroll
        for (int i = tid; i < 1024; i += 256) {
            int r = i >> 3, c8 = (i & 7) * 8;
            size_t ga;
            if (MODE == 2) ga = (size_t)(m0 + r) * (SS * HH) + kc * 64 + c8;
            else           ga = (size_t)(m0 + r) * KTOT + kc * 64 + c8;
            size_t gb = (size_t)(n0 + r) * KTOT + kc * 64 + c8;
            int so = r * GSTR + c8;
            *(uint4*)(Ah + so) = *(const uint4*)(Agh + ga);
            *(uint4*)(Al + so) = *(const uint4*)(Agl + ga);
            *(uint4*)(Bh + so) = *(const uint4*)(Wgh + gb);
            *(uint4*)(Bl + so) = *(const uint4*)(Wgl + gb);
        }
        __syncthreads();

        #pragma unroll
        for (int ks = 0; ks < 4; ks++) {
            int kbase = ks * 16 + 2 * tg;
            uint32_t bh[4][2], bl[4][2];
            #pragma unroll
            for (int nf = 0; nf < 4; nf++) {
                int n = wn + nf * 8 + g;
                bh[nf][0] = *(const uint32_t*)(Bh + n * GSTR + kbase);
                bh[nf][1] = *(const uint32_t*)(Bh + n * GSTR + kbase + 8);
                bl[nf][0] = *(const uint32_t*)(Bl + n * GSTR + kbase);
                bl[nf][1] = *(const uint32_t*)(Bl + n * GSTR + kbase + 8);
            }
            #pragma unroll
            for (int mf = 0; mf < 4; mf++) {
                int r = wm + mf * 16 + g;
                uint32_t ah[4], al[4];
                ah[0] = *(const uint32_t*)(Ah + r * GSTR + kbase);
                ah[1] = *(const uint32_t*)(Ah + (r + 8) * GSTR + kbase);
                ah[2] = *(const uint32_t*)(Ah + r * GSTR + kbase + 8);
                ah[3] = *(const uint32_t*)(Ah + (r + 8) * GSTR + kbase + 8);
                al[0] = *(const uint32_t*)(Al + r * GSTR + kbase);
                al[1] = *(const uint32_t*)(Al + (r + 8) * GSTR + kbase);
                al[2] = *(const uint32_t*)(Al + r * GSTR + kbase + 8);
                al[3] = *(const uint32_t*)(Al + (r + 8) * GSTR + kbase + 8);
                #pragma unroll
                for (int nf = 0; nf < 4; nf++) {
                    mma16816(acc[mf][nf], ah, bh[nf]);
                    mma16816(acc[mf][nf], ah, bl[nf]);
                    mma16816(acc[mf][nf], al, bh[nf]);
                }
            }
        }
        __syncthreads();
    }

    #pragma unroll
    for (int mf = 0; mf < 4; mf++) {
        #pragma unroll
        for (int nf = 0; nf < 4; nf++) {
            int row = m0 + wm + mf * 16 + g;
            int col = n0 + wn + nf * 8 + 2 * tg;
            float b0, b1;
            if (MODE == 1) { b0 = g_bqkv[layer * 128 + col]; b1 = g_bqkv[layer * 128 + col + 1]; }
            else           { b0 = bias[col]; b1 = bias[col + 1]; }
            float2 v0 = make_float2(acc[mf][nf][0] + b0, acc[mf][nf][1] + b1);
            float2 v1 = make_float2(acc[mf][nf][2] + b0, acc[mf][nf][3] + b1);
            if (RELU) {
                v0.x = fmaxf(v0.x, 0.f); v0.y = fmaxf(v0.y, 0.f);
                v1.x = fmaxf(v1.x, 0.f); v1.y = fmaxf(v1.y, 0.f);
            }
            *(float2*)(Cp + (size_t)row * CSTRIDE + col) = v0;
            *(float2*)(Cp + (size_t)(row + 8) * CSTRIDE + col) = v1;
            if (MODE == 0) {   // also emit bf16 hi/lo split of hs
                size_t o0 = (size_t)row * HH + col;
                size_t o1 = (size_t)(row + 8) * HH + col;
                unsigned short h;
                h = f2bf(v0.x); g_hs_hi[o0] = h;     g_hs_lo[o0] = f2bf(v0.x - bf2f(h));
                h = f2bf(v0.y); g_hs_hi[o0 + 1] = h; g_hs_lo[o0 + 1] = f2bf(v0.y - bf2f(h));
                h = f2bf(v1.x); g_hs_hi[o1] = h;     g_hs_lo[o1] = f2bf(v1.x - bf2f(h));
                h = f2bf(v1.y); g_hs_hi[o1 + 1] = h; g_hs_lo[o1 + 1] = f2bf(v1.y - bf2f(h));
            }
        }
    }
}

// ---------------- mask kernel: pm bitmasks from f_frag (= hs after GEMM1) ----------------
__global__ __launch_bounds__(256) void mask_kernel() {
    int b = blockIdx.x;
    int tid = threadIdx.x, w = tid >> 5, lane = tid & 31;
    for (int t = w; t < 512; t += 8) {
        int s = t >> 4, c = t & 15;
        float v = g_hs_f32[((size_t)b * SS + s) * HH + c * 32 + lane];
        unsigned bits = __ballot_sync(0xffffffffu, v > 0.f);
        if (lane == 0) g_pm[(size_t)b * 512 + s * 16 + c] = bits;
    }
}

// ---------------- attn core: scores + mask + softmax + x (per batch) ----------------
__global__ __launch_bounds__(256) void attn_core(float* __restrict__ out,
                                                 int layer) {
    __shared__ float qs[SS * 33], ks[SS * 33], vs[SS * 33], ps[SS * 33];
    __shared__ unsigned pmw[SS * 16];
    int b = blockIdx.x;
    int tid = threadIdx.x, w = tid >> 5, lane = tid & 31;

    for (int i = tid; i < 1024; i += 256) {
        int s = i >> 5, d = i & 31;
        const float* base = g_qkv + ((size_t)b * SS + s) * 128;
        qs[s * 33 + d] = base[d];
        ks[s * 33 + d] = base[32 + d];
        vs[s * 33 + d] = base[64 + d];
    }
    for (int i = tid; i < 512; i += 256) pmw[i] = g_pm[(size_t)b * 512 + i];
    __syncthreads();

    #pragma unroll
    for (int j = 0; j < 4; j++) {
        int idx = tid + 256 * j;
        int s = idx >> 5, t = idx & 31;
        float a = 0.f;
        #pragma unroll 8
        for (int d = 0; d < 32; d++)
            a = fmaf(qs[s * 33 + d], ks[t * 33 + d], a);
        a *= 0.17677669529663687f;
        unsigned ored = 0;
        #pragma unroll
        for (int i = 0; i < 16; i++) ored |= pmw[s * 16 + i] & pmw[t * 16 + i];
        ps[s * 33 + t] = ored ? a : -1e9f;
    }
    __syncthreads();

    #pragma unroll
    for (int i = 0; i < 4; i++) {
        int s = w + 8 * i;
        float a = ps[s * 33 + lane];
        float mval = a;
        #pragma unroll
        for (int o = 16; o > 0; o >>= 1)
            mval = fmaxf(mval, __shfl_xor_sync(0xffffffffu, mval, o));
        float e = __expf(a - mval);
        float ssum = e;
        #pragma unroll
        for (int o = 16; o > 0; o >>= 1)
            ssum += __shfl_xor_sync(0xffffffffu, ssum, o);
        float pr = e / ssum;
        ps[s * 33 + lane] = pr;
        if (layer == 1)
            out[(size_t)BB * HH + ((size_t)b * SS + s) * SS + lane] = pr;
    }
    __syncthreads();

    #pragma unroll
    for (int j = 0; j < 4; j++) {
        int idx = tid + 256 * j;
        int s = idx >> 5, d = idx & 31;
        float a = 0.f;
        #pragma unroll 8
        for (int t = 0; t < 32; t++)
            a = fmaf(ps[s * 33 + t], vs[t * 33 + d], a);
        unsigned short h = f2bf(a);
        size_t o = ((size_t)b * SS + s) * 64 + d;
        g_x_hi[o] = h;
        g_x_lo[o] = f2bf(a - bf2f(h));
    }
}

// ---------------- residual + layernorm kernel (per (b,s) row) ----------------
__global__ __launch_bounds__(128) void resid_ln(
    const float* __restrict__ ln_g, const float* __restrict__ ln_b, int layer) {
    __shared__ float red[8];
    size_t r = blockIdx.x;
    int tid = threadIdx.x, w = tid >> 5, lane = tid & 31;
    float v[4];
    #pragma unroll
    for (int j = 0; j < 4; j++) {
        int h = tid + 128 * j;
        v[j] = g_dh[r * HH + h] + g_hs_f32[r * HH + h];
    }
    float sum = v[0] + v[1] + v[2] + v[3];
    #pragma unroll
    for (int o = 16; o > 0; o >>= 1) sum += __shfl_xor_sync(0xffffffffu, sum, o);
    if (lane == 0) red[w] = sum;
    __syncthreads();
    float mu = (red[0] + red[1] + red[2] + red[3]) * (1.f / 512.f);
    __syncthreads();
    float q = 0.f;
    #pragma unroll
    for (int j = 0; j < 4; j++) { float d = v[j] - mu; q = fmaf(d, d, q); }
    #pragma unroll
    for (int o = 16; o > 0; o >>= 1) q += __shfl_xor_sync(0xffffffffu, q, o);
    if (lane == 0) red[w] = q;
    __syncthreads();
    float rstd = rsqrtf((red[0] + red[1] + red[2] + red[3]) * (1.f / 512.f) + 1e-6f);
    #pragma unroll
    for (int j = 0; j < 4; j++) {
        int h = tid + 128 * j;
        float nv = ln_g[layer * HH + h] * (v[j] - mu) * rstd + ln_b[layer * HH + h];
        g_hs_f32[r * HH + h] = nv;
        unsigned short hb = f2bf(nv);
        g_hs_hi[r * HH + h] = hb;
        g_hs_lo[r * HH + h] = f2bf(nv - bf2f(hb));
    }
}

// ---------------- final layernorm * alpha (in-place on d_out) ----------------
__global__ __launch_bounds__(256) void final_ln(
    const float* __restrict__ ng, const float* __restrict__ nb,
    const float* __restrict__ alpha, float* __restrict__ out) {
    __shared__ float red[16];
    int b = blockIdx.x, tid = threadIdx.x, w = tid >> 5, lane = tid & 31;
    float* row = out + (size_t)b * HH;
    float v0 = row[tid], v1 = row[tid + 256];
    float sum = v0 + v1;
    #pragma unroll
    for (int o = 16; o > 0; o >>= 1) sum += __shfl_xor_sync(0xffffffffu, sum, o);
    if (lane == 0) red[w] = sum;
    __syncthreads();
    if (tid == 0) {
        float t = 0.f;
        #pragma unroll
        for (int i = 0; i < 8; i++) t += red[i];
        red[8] = t * (1.f / 512.f);
    }
    __syncthreads();
    float mu = red[8];
    float d0 = v0 - mu, d1 = v1 - mu;
    float qq = d0 * d0 + d1 * d1;
    #pragma unroll
    for (int o = 16; o > 0; o >>= 1) qq += __shfl_xor_sync(0xffffffffu, qq, o);
    if (lane == 0) red[w] = qq;
    __syncthreads();
    if (tid == 0) {
        float t = 0.f;
        #pragma unroll
        for (int i = 0; i < 8; i++) t += red[i];
        red[9] = rsqrtf(t * (1.f / 512.f) + 1e-5f);
    }
    __syncthreads();
    float rstd = red[9];
    float a = alpha[0];
    row[tid] = (ng[tid] * d0 * rstd + nb[tid]) * a;
    row[tid + 256] = (ng[tid + 256] * d1 * rstd + nb[tid + 256]) * a;
}

// ---------------- launcher ----------------
extern "C" void kernel_launch(void* const* d_in, const int* in_sizes, int n_in,
                              void* d_out, int out_size) {
    const float* f_atom   = (const float*)d_in[0];
    const float* f_group  = (const float*)d_in[1];
    const float* fg       = (const float*)d_in[2];
    const float* alpha    = (const float*)d_in[3];
    const float* lr_w     = (const float*)d_in[4];
    const float* lr_b     = (const float*)d_in[5];
    const float* wq_w     = (const float*)d_in[6];
    const float* wq_b     = (const float*)d_in[7];
    const float* wk_w     = (const float*)d_in[8];
    const float* wk_b     = (const float*)d_in[9];
    const float* wv_w     = (const float*)d_in[10];
    const float* wv_b     = (const float*)d_in[11];
    const float* dense_w  = (const float*)d_in[12];
    const float* dense_b  = (const float*)d_in[13];
    const float* ln_g     = (const float*)d_in[14];
    const float* ln_b     = (const float*)d_in[15];
    const float* lin_w    = (const float*)d_in[16];
    const float* lin_b    = (const float*)d_in[17];
    const float* norm_g   = (const float*)d_in[18];
    const float* norm_b   = (const float*)d_in[19];
    const int* mapping    = (const int*)d_in[20];   // int32 (JAX x64 disabled)
    float* out = (float*)d_out;

    cudaFuncSetAttribute(gemm_mma<0>, cudaFuncAttributeMaxDynamicSharedMemorySize,
                         TCSM_BYTES);
    cudaFuncSetAttribute(gemm_mma<1>, cudaFuncAttributeMaxDynamicSharedMemorySize,
                         TCSM_BYTES);
    cudaFuncSetAttribute(gemm_mma<2>, cudaFuncAttributeMaxDynamicSharedMemorySize,
                         TCSM_BYTES);
    cudaFuncSetAttribute(gemm_mma<3>, cudaFuncAttributeMaxDynamicSharedMemorySize,
                         TCSM_BYTES);

    // 0) weight packing / split
    convert_weights<<<(K3H * HH) / 256, 256>>>(lr_w, lin_w, wq_w, wq_b, wk_w,
                                               wk_b, wv_w, wv_b, dense_w);
    // 1) brics
    build_brics<<<BB * SS, 128>>>(f_atom, f_group, fg, mapping);
    // 2) hs = relu(brics @ lr_w + lr_b), + hi/lo split
    gemm_mma<0><<<dim3(4, (BB * SS) / 128), 256, TCSM_BYTES>>>(lr_b, nullptr, 0);
    // 3) pm masks (from layer-0 input)
    mask_kernel<<<BB, 256>>>();
    // 4) two transformer layers
    for (int l = 0; l < 2; l++) {
        gemm_mma<1><<<dim3(1, (BB * SS) / 128), 256, TCSM_BYTES>>>(nullptr,
                                                                   nullptr, l);
        attn_core<<<BB, 256>>>(out, l);
        gemm_mma<3><<<dim3(4, (BB * SS) / 128), 256, TCSM_BYTES>>>(dense_b + l * HH,
                                                                   nullptr, l);
        resid_ln<<<BB * SS, 128>>>(ln_g, ln_b, l);
    }
    // 5) final projection on row 0 only
    gemm_mma<2><<<dim3(4, BB / 128), 256, TCSM_BYTES>>>(lin_b, out, 0);
    // 6) final layernorm * alpha
    final_ln<<<BB, 256>>>(norm_g, norm_b, alpha, out);
}

// round 16
// speedup vs baseline: 2.9752x; 1.4018x over previous
#include <cuda_runtime.h>
#include <cuda_bf16.h>
#include <cstdint>

#define BB 1024
#define AA 64
#define GG 31
#define WWIN 8
#define HH 512
#define SS 32
#define DKK 32
#define K3H 1536

// ---------------- scratch (static device globals; no allocation) ----------------
__device__ unsigned short g_a_hi[(size_t)BB * SS * K3H];   // brics hi
__device__ unsigned short g_a_lo[(size_t)BB * SS * K3H];   // brics lo
__device__ float          g_hs_f32[(size_t)BB * SS * HH];  // current hs (fp32)
__device__ unsigned short g_hs_hi[(size_t)BB * SS * HH];   // current hs bf16 split
__device__ unsigned short g_hs_lo[(size_t)BB * SS * HH];
__device__ float          g_qkv[(size_t)BB * SS * 128];    // packed q|k|v (+pad)
__device__ unsigned short g_x_hi[(size_t)BB * SS * 64];    // attn x, zero-padded K
__device__ unsigned short g_x_lo[(size_t)BB * SS * 64];
__device__ float          g_dh[(size_t)BB * SS * HH];      // dense output
__device__ unsigned int   g_pm[(size_t)BB * SS * 16];      // sign bitmasks
__device__ unsigned short g_wb_hi[(size_t)HH * K3H];       // lr_w  [n][k]
__device__ unsigned short g_wb_lo[(size_t)HH * K3H];
__device__ unsigned short g_wf_hi[(size_t)HH * HH];        // lin_w [n][k]
__device__ unsigned short g_wf_lo[(size_t)HH * HH];
__device__ unsigned short g_wqkv_hi[(size_t)2 * 128 * HH]; // qkv packed [l][n][k]
__device__ unsigned short g_wqkv_lo[(size_t)2 * 128 * HH];
__device__ float          g_bqkv[2 * 128];                 // qkv packed bias
__device__ unsigned short g_wd_hi[(size_t)2 * HH * 64];    // dense [l][n][64pad]
__device__ unsigned short g_wd_lo[(size_t)2 * HH * 64];

// ---------------- helpers ----------------
__device__ __forceinline__ unsigned short f2bf(float f) {
    return __bfloat16_as_ushort(__float2bfloat16(f));
}
__device__ __forceinline__ float bf2f(unsigned short u) {
    return __bfloat162float(__ushort_as_bfloat16(u));
}
__device__ __forceinline__ void mma16816(float* c, const uint32_t* a,
                                         const uint32_t* b) {
    asm volatile(
        "mma.sync.aligned.m16n8k16.row.col.f32.bf16.bf16.f32 "
        "{%0,%1,%2,%3}, {%4,%5,%6,%7}, {%8,%9}, {%0,%1,%2,%3};"
        : "+f"(c[0]), "+f"(c[1]), "+f"(c[2]), "+f"(c[3])
        : "r"(a[0]), "r"(a[1]), "r"(a[2]), "r"(a[3]), "r"(b[0]), "r"(b[1]));
}
__device__ __forceinline__ uint32_t smem_cvta(const void* p) {
    uint32_t a;
    asm("{ .reg .u64 t; cvta.to.shared.u64 t, %1; cvt.u32.u64 %0, t; }"
        : "=r"(a) : "l"(p));
    return a;
}
__device__ __forceinline__ void cp16(void* sdst, const void* gsrc) {
    asm volatile("cp.async.cg.shared.global [%0], [%1], 16;"
                 :: "r"(smem_cvta(sdst)), "l"(gsrc));
}
__device__ __forceinline__ void cp_commit() {
    asm volatile("cp.async.commit_group;" ::: "memory");
}
__device__ __forceinline__ void cp_wait0() {
    asm volatile("cp.async.wait_group 0;" ::: "memory");
}

// ---------------- Kernel 0: one-time weight packing/splitting ----------------
__global__ __launch_bounds__(256) void convert_weights(
    const float* __restrict__ lr_w, const float* __restrict__ lin_w,
    const float* __restrict__ wq_w, const float* __restrict__ wq_b,
    const float* __restrict__ wk_w, const float* __restrict__ wk_b,
    const float* __restrict__ wv_w, const float* __restrict__ wv_b,
    const float* __restrict__ dense_w) {
    int t = blockIdx.x * 256 + threadIdx.x;
    if (t < K3H * HH) {
        int k = t / HH, n = t % HH;
        float f = lr_w[t];
        unsigned short h = f2bf(f);
        g_wb_hi[(size_t)n * K3H + k] = h;
        g_wb_lo[(size_t)n * K3H + k] = f2bf(f - bf2f(h));
    }
    if (t < HH * HH) {
        int k = t / HH, n = t % HH;
        float f = lin_w[t];
        unsigned short h = f2bf(f);
        g_wf_hi[(size_t)n * HH + k] = h;
        g_wf_lo[(size_t)n * HH + k] = f2bf(f - bf2f(h));
    }
    if (t < 2 * 128 * HH) {
        int l = t / (128 * HH);
        int r = t % (128 * HH);
        int n = r / HH, k = r % HH;
        float f = 0.f;
        if (n < 32)       f = wq_w[(size_t)l * HH * DKK + k * DKK + n];
        else if (n < 64)  f = wk_w[(size_t)l * HH * DKK + k * DKK + (n - 32)];
        else if (n < 96)  f = wv_w[(size_t)l * HH * DKK + k * DKK + (n - 64)];
        unsigned short h = f2bf(f);
        g_wqkv_hi[t] = h;
        g_wqkv_lo[t] = f2bf(f - bf2f(h));
    }
    if (t < 2 * 128) {
        int l = t / 128, n = t % 128;
        float f = 0.f;
        if (n < 32)       f = wq_b[l * DKK + n];
        else if (n < 64)  f = wk_b[l * DKK + (n - 32)];
        else if (n < 96)  f = wv_b[l * DKK + (n - 64)];
        g_bqkv[t] = f;
    }
    if (t < 2 * HH * 64) {
        int l = t / (HH * 64);
        int r = t % (HH * 64);
        int n = r / 64, k = r % 64;
        float f = (k < DKK) ? dense_w[(size_t)l * DKK * HH + k * HH + n] : 0.f;
        unsigned short h = f2bf(f);
        g_wd_hi[t] = h;
        g_wd_lo[t] = f2bf(f - bf2f(h));
    }
}

// ---------------- Kernel 1: build brics (bf16 hi/lo) ----------------
__global__ __launch_bounds__(128) void build_brics(
    const float* __restrict__ f_atom, const float* __restrict__ f_group,
    const float* __restrict__ fg, const int* __restrict__ mapping) {
    int bs = blockIdx.x;
    int b = bs >> 5, s = bs & 31;
    int tid = threadIdx.x;
    unsigned short* dh = g_a_hi + (size_t)bs * K3H;
    unsigned short* dl = g_a_lo + (size_t)bs * K3H;

    float4 secs[3];
    if (s == 0) {
        secs[0] = ((const float4*)fg)[tid];
        secs[1] = ((const float4*)fg)[tid + 128];
        secs[2] = ((const float4*)fg)[tid + 256];
    } else {
        int g = s - 1;
        const int* mp = mapping + ((size_t)b * GG + g) * WWIN;
        int idx[WWIN];
        #pragma unroll
        for (int w = 0; w < WWIN; w++) idx[w] = mp[w];
        float4 sm = make_float4(0.f, 0.f, 0.f, 0.f);
        float4 mx = make_float4(-3.4e38f, -3.4e38f, -3.4e38f, -3.4e38f);
        #pragma unroll
        for (int w = 0; w < WWIN; w++) {
            float4 v;
            if (idx[w] == 0) v = make_float4(0.f, 0.f, 0.f, 0.f);
            else v = ((const float4*)(f_atom + ((size_t)b * AA + idx[w] - 1) * HH))[tid];
            sm.x += v.x; sm.y += v.y; sm.z += v.z; sm.w += v.w;
            mx.x = fmaxf(mx.x, v.x); mx.y = fmaxf(mx.y, v.y);
            mx.z = fmaxf(mx.z, v.z); mx.w = fmaxf(mx.w, v.w);
        }
        secs[0] = sm;
        secs[1] = mx;
        secs[2] = ((const float4*)(f_group + ((size_t)b * GG + g) * HH))[tid];
    }
    #pragma unroll
    for (int sec = 0; sec < 3; sec++) {
        float v[4] = {secs[sec].x, secs[sec].y, secs[sec].z, secs[sec].w};
        unsigned short h[4], l[4];
        #pragma unroll
        for (int j = 0; j < 4; j++) {
            h[j] = f2bf(v[j]);
            l[j] = f2bf(v[j] - bf2f(h[j]));
        }
        int off = sec * HH + tid * 4;
        *(uint2*)(dh + off) = make_uint2((uint32_t)h[0] | ((uint32_t)h[1] << 16),
                                         (uint32_t)h[2] | ((uint32_t)h[3] << 16));
        *(uint2*)(dl + off) = make_uint2((uint32_t)l[0] | ((uint32_t)l[1] << 16),
                                         (uint32_t)l[2] | ((uint32_t)l[3] << 16));
    }
}

// ---------------- mma.sync split-bf16 GEMM, cp.async double-buffered ----------------
// MODE 0: hs = relu(brics@lr_w+lr_b)  K=1536
// MODE 1: qkv = hs@Wqkv+bqkv          K=512, C stride 128
// MODE 2: out = hs[s=0]@lin_w+lin_b   K=512, A row stride SS*HH
// MODE 3: dh  = x@Wd+dense_b          K=64
// MODE 4: dh[s=0] = x[s=0]@Wd+dense_b K=64, A stride SS*64, C stride SS*HH
#define BK 32
#define GSTR2 40                          // padded stride (shorts); conflict-free
#define STG_SH (4 * 128 * GSTR2)          // shorts per stage
#define TCSM_BYTES (2 * STG_SH * 2)       // 81920 bytes

template <int MODE>
__global__ __launch_bounds__(256) void gemm_mma(
    const float* __restrict__ bias, float* __restrict__ Cout, int layer) {
    constexpr int KTOT = (MODE == 0) ? K3H : (MODE >= 3) ? 64 : HH;
    constexpr int NCH = KTOT / BK;
    constexpr bool RELU = (MODE == 0);
    constexpr int ASTR = (MODE == 0) ? K3H : (MODE == 1) ? HH
                        : (MODE == 2) ? SS * HH : (MODE == 3) ? 64 : SS * 64;
    constexpr int CSTR = (MODE == 1) ? 128 : (MODE == 4) ? SS * HH : HH;

    extern __shared__ unsigned short smem[];

    const unsigned short* Agh;
    const unsigned short* Agl;
    const unsigned short* Wgh;
    const unsigned short* Wgl;
    float* Cp;
    if (MODE == 0) { Agh = g_a_hi;  Agl = g_a_lo;  Wgh = g_wb_hi; Wgl = g_wb_lo; Cp = g_hs_f32; }
    else if (MODE == 1) {
        Agh = g_hs_hi; Agl = g_hs_lo;
        Wgh = g_wqkv_hi + (size_t)layer * 128 * HH;
        Wgl = g_wqkv_lo + (size_t)layer * 128 * HH;
        Cp = g_qkv;
    } else if (MODE == 2) { Agh = g_hs_hi; Agl = g_hs_lo; Wgh = g_wf_hi; Wgl = g_wf_lo; Cp = Cout; }
    else {
        Agh = g_x_hi; Agl = g_x_lo;
        Wgh = g_wd_hi + (size_t)layer * HH * 64;
        Wgl = g_wd_lo + (size_t)layer * HH * 64;
        Cp = g_dh;
    }

    int tid = threadIdx.x, wid = tid >> 5, lane = tid & 31;
    int m0 = blockIdx.y * 128, n0 = blockIdx.x * 128;
    int wm = (wid & 1) * 64;
    int wn = (wid >> 1) * 32;
    int g = lane >> 2, tg = lane & 3;

    float acc[4][4][4];
    #pragma unroll
    for (int i = 0; i < 4; i++)
        #pragma unroll
        for (int j = 0; j < 4; j++)
            #pragma unroll
            for (int c = 0; c < 4; c++) acc[i][j][c] = 0.f;

    // stage loader: 4 arrays x 128 rows x 32 shorts (4 uint4/row)
    auto load_stage = [&](int st, int kc) {
        unsigned short* Ah = smem + st * STG_SH;
        unsigned short* Al = Ah + 128 * GSTR2;
        unsigned short* Bh = Al + 128 * GSTR2;
        unsigned short* Bl = Bh + 128 * GSTR2;
        #pragma unroll
        for (int i = tid; i < 512; i += 256) {
            int r = i >> 2, c8 = (i & 3) * 8;
            size_t ga = (size_t)(m0 + r) * ASTR + kc * BK + c8;
            size_t gb = (size_t)(n0 + r) * KTOT + kc * BK + c8;
            int so = r * GSTR2 + c8;
            cp16(Ah + so, Agh + ga);
            cp16(Al + so, Agl + ga);
            cp16(Bh + so, Wgh + gb);
            cp16(Bl + so, Wgl + gb);
        }
        cp_commit();
    };

    load_stage(0, 0);
    for (int kc = 0; kc < NCH; kc++) {
        cp_wait0();
        __syncthreads();
        if (kc + 1 < NCH) load_stage((kc + 1) & 1, kc + 1);

        unsigned short* Ah = smem + (kc & 1) * STG_SH;
        unsigned short* Al = Ah + 128 * GSTR2;
        unsigned short* Bh = Al + 128 * GSTR2;
        unsigned short* Bl = Bh + 128 * GSTR2;

        #pragma unroll
        for (int ks = 0; ks < 2; ks++) {
            int kbase = ks * 16 + 2 * tg;
            uint32_t bh[4][2], bl[4][2];
            #pragma unroll
            for (int nf = 0; nf < 4; nf++) {
                int n = wn + nf * 8 + g;
                bh[nf][0] = *(const uint32_t*)(Bh + n * GSTR2 + kbase);
                bh[nf][1] = *(const uint32_t*)(Bh + n * GSTR2 + kbase + 8);
                bl[nf][0] = *(const uint32_t*)(Bl + n * GSTR2 + kbase);
                bl[nf][1] = *(const uint32_t*)(Bl + n * GSTR2 + kbase + 8);
            }
            #pragma unroll
            for (int mf = 0; mf < 4; mf++) {
                int r = wm + mf * 16 + g;
                uint32_t ah[4], al[4];
                ah[0] = *(const uint32_t*)(Ah + r * GSTR2 + kbase);
                ah[1] = *(const uint32_t*)(Ah + (r + 8) * GSTR2 + kbase);
                ah[2] = *(const uint32_t*)(Ah + r * GSTR2 + kbase + 8);
                ah[3] = *(const uint32_t*)(Ah + (r + 8) * GSTR2 + kbase + 8);
                al[0] = *(const uint32_t*)(Al + r * GSTR2 + kbase);
                al[1] = *(const uint32_t*)(Al + (r + 8) * GSTR2 + kbase);
                al[2] = *(const uint32_t*)(Al + r * GSTR2 + kbase + 8);
                al[3] = *(const uint32_t*)(Al + (r + 8) * GSTR2 + kbase + 8);
                #pragma unroll
                for (int nf = 0; nf < 4; nf++) {
                    mma16816(acc[mf][nf], ah, bh[nf]);
                    mma16816(acc[mf][nf], ah, bl[nf]);
                    mma16816(acc[mf][nf], al, bh[nf]);
                }
            }
        }
        __syncthreads();
    }

    #pragma unroll
    for (int mf = 0; mf < 4; mf++) {
        #pragma unroll
        for (int nf = 0; nf < 4; nf++) {
            int row = m0 + wm + mf * 16 + g;
            int col = n0 + wn + nf * 8 + 2 * tg;
            float b0, b1;
            if (MODE == 1) { b0 = g_bqkv[layer * 128 + col]; b1 = g_bqkv[layer * 128 + col + 1]; }
            else           { b0 = bias[col]; b1 = bias[col + 1]; }
            float2 v0 = make_float2(acc[mf][nf][0] + b0, acc[mf][nf][1] + b1);
            float2 v1 = make_float2(acc[mf][nf][2] + b0, acc[mf][nf][3] + b1);
            if (RELU) {
                v0.x = fmaxf(v0.x, 0.f); v0.y = fmaxf(v0.y, 0.f);
                v1.x = fmaxf(v1.x, 0.f); v1.y = fmaxf(v1.y, 0.f);
            }
            *(float2*)(Cp + (size_t)row * CSTR + col) = v0;
            *(float2*)(Cp + (size_t)(row + 8) * CSTR + col) = v1;
            if (MODE == 0) {
                size_t o0 = (size_t)row * HH + col;
                size_t o1 = (size_t)(row + 8) * HH + col;
                unsigned short h;
                h = f2bf(v0.x); g_hs_hi[o0] = h;     g_hs_lo[o0] = f2bf(v0.x - bf2f(h));
                h = f2bf(v0.y); g_hs_hi[o0 + 1] = h; g_hs_lo[o0 + 1] = f2bf(v0.y - bf2f(h));
                h = f2bf(v1.x); g_hs_hi[o1] = h;     g_hs_lo[o1] = f2bf(v1.x - bf2f(h));
                h = f2bf(v1.y); g_hs_hi[o1 + 1] = h; g_hs_lo[o1 + 1] = f2bf(v1.y - bf2f(h));
            }
        }
    }
}

// ---------------- mask kernel: vectorized ballot-free bit assembly ----------------
__global__ __launch_bounds__(256) void mask_kernel() {
    int b = blockIdx.x;
    int tid = threadIdx.x, w = tid >> 5, lane = tid & 31;
    #pragma unroll
    for (int i = 0; i < 4; i++) {
        int s = w + 8 * i;
        const float4* row = (const float4*)(g_hs_f32 + ((size_t)b * SS + s) * HH);
        #pragma unroll
        for (int j = 0; j < 4; j++) {
            float4 v = row[lane + 32 * j];
            unsigned nib = (v.x > 0.f ? 1u : 0u) | (v.y > 0.f ? 2u : 0u) |
                           (v.z > 0.f ? 4u : 0u) | (v.w > 0.f ? 8u : 0u);
            unsigned word = nib << (4 * (lane & 7));
            word |= __shfl_xor_sync(0xffffffffu, word, 1);
            word |= __shfl_xor_sync(0xffffffffu, word, 2);
            word |= __shfl_xor_sync(0xffffffffu, word, 4);
            if ((lane & 7) == 0)
                g_pm[(size_t)b * 512 + s * 16 + j * 4 + (lane >> 3)] = word;
        }
    }
}

// ---------------- attn core: scores + mask + softmax + x (per batch) ----------------
__global__ __launch_bounds__(256) void attn_core(float* __restrict__ out,
                                                 int layer) {
    __shared__ float qs[SS * 33], ks[SS * 33], vs[SS * 33], ps[SS * 33];
    __shared__ unsigned pmw[SS * 16];
    int b = blockIdx.x;
    int tid = threadIdx.x, w = tid >> 5, lane = tid & 31;

    for (int i = tid; i < 1024; i += 256) {
        int s = i >> 5, d = i & 31;
        const float* base = g_qkv + ((size_t)b * SS + s) * 128;
        qs[s * 33 + d] = base[d];
        ks[s * 33 + d] = base[32 + d];
        vs[s * 33 + d] = base[64 + d];
    }
    for (int i = tid; i < 512; i += 256) pmw[i] = g_pm[(size_t)b * 512 + i];
    __syncthreads();

    #pragma unroll
    for (int j = 0; j < 4; j++) {
        int idx = tid + 256 * j;
        int s = idx >> 5, t = idx & 31;
        float a = 0.f;
        #pragma unroll 8
        for (int d = 0; d < 32; d++)
            a = fmaf(qs[s * 33 + d], ks[t * 33 + d], a);
        a *= 0.17677669529663687f;
        unsigned ored = 0;
        #pragma unroll
        for (int i = 0; i < 16; i++) ored |= pmw[s * 16 + i] & pmw[t * 16 + i];
        ps[s * 33 + t] = ored ? a : -1e9f;
    }
    __syncthreads();

    #pragma unroll
    for (int i = 0; i < 4; i++) {
        int s = w + 8 * i;
        float a = ps[s * 33 + lane];
        float mval = a;
        #pragma unroll
        for (int o = 16; o > 0; o >>= 1)
            mval = fmaxf(mval, __shfl_xor_sync(0xffffffffu, mval, o));
        float e = __expf(a - mval);
        float ssum = e;
        #pragma unroll
        for (int o = 16; o > 0; o >>= 1)
            ssum += __shfl_xor_sync(0xffffffffu, ssum, o);
        float pr = e / ssum;
        ps[s * 33 + lane] = pr;
        if (layer == 1)
            out[(size_t)BB * HH + ((size_t)b * SS + s) * SS + lane] = pr;
    }
    __syncthreads();

    #pragma unroll
    for (int j = 0; j < 4; j++) {
        int idx = tid + 256 * j;
        int s = idx >> 5, d = idx & 31;
        float a = 0.f;
        #pragma unroll 8
        for (int t = 0; t < 32; t++)
            a = fmaf(ps[s * 33 + t], vs[t * 33 + d], a);
        unsigned short h = f2bf(a);
        size_t o = ((size_t)b * SS + s) * 64 + d;
        g_x_hi[o] = h;
        g_x_lo[o] = f2bf(a - bf2f(h));
    }
}

// ---------------- residual + layernorm (LAST: only s=0 rows, no f32 writeback) ---
template <bool LAST>
__global__ __launch_bounds__(128) void resid_ln(
    const float* __restrict__ ln_g, const float* __restrict__ ln_b, int layer) {
    __shared__ float red[8];
    size_t r = LAST ? (size_t)blockIdx.x * SS : (size_t)blockIdx.x;
    int tid = threadIdx.x, w = tid >> 5, lane = tid & 31;
    float v[4];
    #pragma unroll
    for (int j = 0; j < 4; j++) {
        int h = tid + 128 * j;
        v[j] = g_dh[r * HH + h] + g_hs_f32[r * HH + h];
    }
    float sum = v[0] + v[1] + v[2] + v[3];
    #pragma unroll
    for (int o = 16; o > 0; o >>= 1) sum += __shfl_xor_sync(0xffffffffu, sum, o);
    if (lane == 0) red[w] = sum;
    __syncthreads();
    float mu = (red[0] + red[1] + red[2] + red[3]) * (1.f / 512.f);
    __syncthreads();
    float q = 0.f;
    #pragma unroll
    for (int j = 0; j < 4; j++) { float d = v[j] - mu; q = fmaf(d, d, q); }
    #pragma unroll
    for (int o = 16; o > 0; o >>= 1) q += __shfl_xor_sync(0xffffffffu, q, o);
    if (lane == 0) red[w] = q;
    __syncthreads();
    float rstd = rsqrtf((red[0] + red[1] + red[2] + red[3]) * (1.f / 512.f) + 1e-6f);
    #pragma unroll
    for (int j = 0; j < 4; j++) {
        int h = tid + 128 * j;
        float nv = ln_g[layer * HH + h] * (v[j] - mu) * rstd + ln_b[layer * HH + h];
        if (!LAST) g_hs_f32[r * HH + h] = nv;
        unsigned short hb = f2bf(nv);
        g_hs_hi[r * HH + h] = hb;
        g_hs_lo[r * HH + h] = f2bf(nv - bf2f(hb));
    }
}

// ---------------- final layernorm * alpha (in-place on d_out) ----------------
__global__ __launch_bounds__(256) void final_ln(
    const float* __restrict__ ng, const float* __restrict__ nb,
    const float* __restrict__ alpha, float* __restrict__ out) {
    __shared__ float red[16];
    int b = blockIdx.x, tid = threadIdx.x, w = tid >> 5, lane = tid & 31;
    float* row = out + (size_t)b * HH;
    float v0 = row[tid], v1 = row[tid + 256];
    float sum = v0 + v1;
    #pragma unroll
    for (int o = 16; o > 0; o >>= 1) sum += __shfl_xor_sync(0xffffffffu, sum, o);
    if (lane == 0) red[w] = sum;
    __syncthreads();
    if (tid == 0) {
        float t = 0.f;
        #pragma unroll
        for (int i = 0; i < 8; i++) t += red[i];
        red[8] = t * (1.f / 512.f);
    }
    __syncthreads();
    float mu = red[8];
    float d0 = v0 - mu, d1 = v1 - mu;
    float qq = d0 * d0 + d1 * d1;
    #pragma unroll
    for (int o = 16; o > 0; o >>= 1) qq += __shfl_xor_sync(0xffffffffu, qq, o);
    if (lane == 0) red[w] = qq;
    __syncthreads();
    if (tid == 0) {
        float t = 0.f;
        #pragma unroll
        for (int i = 0; i < 8; i++) t += red[i];
        red[9] = rsqrtf(t * (1.f / 512.f) + 1e-5f);
    }
    __syncthreads();
    float rstd = red[9];
    float a = alpha[0];
    row[tid] = (ng[tid] * d0 * rstd + nb[tid]) * a;
    row[tid + 256] = (ng[tid + 256] * d1 * rstd + nb[tid + 256]) * a;
}

// ---------------- launcher ----------------
extern "C" void kernel_launch(void* const* d_in, const int* in_sizes, int n_in,
                              void* d_out, int out_size) {
    const float* f_atom   = (const float*)d_in[0];
    const float* f_group  = (const float*)d_in[1];
    const float* fg       = (const float*)d_in[2];
    const float* alpha    = (const float*)d_in[3];
    const float* lr_w     = (const float*)d_in[4];
    const float* lr_b     = (const float*)d_in[5];
    const float* wq_w     = (const float*)d_in[6];
    const float* wq_b     = (const float*)d_in[7];
    const float* wk_w     = (const float*)d_in[8];
    const float* wk_b     = (const float*)d_in[9];
    const float* wv_w     = (const float*)d_in[10];
    const float* wv_b     = (const float*)d_in[11];
    const float* dense_w  = (const float*)d_in[12];
    const float* dense_b  = (const float*)d_in[13];
    const float* ln_g     = (const float*)d_in[14];
    const float* ln_b     = (const float*)d_in[15];
    const float* lin_w    = (const float*)d_in[16];
    const float* lin_b    = (const float*)d_in[17];
    const float* norm_g   = (const float*)d_in[18];
    const float* norm_b   = (const float*)d_in[19];
    const int* mapping    = (const int*)d_in[20];   // int32 (JAX x64 disabled)
    float* out = (float*)d_out;

    cudaFuncSetAttribute(gemm_mma<0>, cudaFuncAttributeMaxDynamicSharedMemorySize,
                         TCSM_BYTES);
    cudaFuncSetAttribute(gemm_mma<1>, cudaFuncAttributeMaxDynamicSharedMemorySize,
                         TCSM_BYTES);
    cudaFuncSetAttribute(gemm_mma<2>, cudaFuncAttributeMaxDynamicSharedMemorySize,
                         TCSM_BYTES);
    cudaFuncSetAttribute(gemm_mma<3>, cudaFuncAttributeMaxDynamicSharedMemorySize,
                         TCSM_BYTES);
    cudaFuncSetAttribute(gemm_mma<4>, cudaFuncAttributeMaxDynamicSharedMemorySize,
                         TCSM_BYTES);

    convert_weights<<<(K3H * HH) / 256, 256>>>(lr_w, lin_w, wq_w, wq_b, wk_w,
                                               wk_b, wv_w, wv_b, dense_w);
    build_brics<<<BB * SS, 128>>>(f_atom, f_group, fg, mapping);
    gemm_mma<0><<<dim3(4, (BB * SS) / 128), 256, TCSM_BYTES>>>(lr_b, nullptr, 0);
    mask_kernel<<<BB, 256>>>();

    // layer 0 (full)
    gemm_mma<1><<<dim3(1, (BB * SS) / 128), 256, TCSM_BYTES>>>(nullptr, nullptr, 0);
    attn_core<<<BB, 256>>>(out, 0);
    gemm_mma<3><<<dim3(4, (BB * SS) / 128), 256, TCSM_BYTES>>>(dense_b, nullptr, 0);
    resid_ln<false><<<BB * SS, 128>>>(ln_g, ln_b, 0);

    // layer 1 (only s=0 rows matter after attn output)
    gemm_mma<1><<<dim3(1, (BB * SS) / 128), 256, TCSM_BYTES>>>(nullptr, nullptr, 1);
    attn_core<<<BB, 256>>>(out, 1);
    gemm_mma<4><<<dim3(4, BB / 128), 256, TCSM_BYTES>>>(dense_b + HH, nullptr, 1);
    resid_ln<true><<<BB, 128>>>(ln_g, ln_b, 1);

    gemm_mma<2><<<dim3(4, BB / 128), 256, TCSM_BYTES>>>(lin_b, out, 0);
    final_ln<<<BB, 256>>>(norm_g, norm_b, alpha, out);
}